// round 13
// baseline (speedup 1.0000x reference)
#include <cuda_runtime.h>
#include <math.h>
#include <stdint.h>

// ============================================================
// ReliabilityGatedCrossAttention  (B=4, N=1024, DIM=1024, H=16, d=64)
// All matmuls: mma.sync m16n8k8 tf32.  tf32 rounding at producers
// (fast ILP conv kernels / epilogues).  GEMM: 3-stage cp.async
// pipeline, 1 sync per k-tile, 2 CTAs/SM.  Flash: R9 proven design.
// ============================================================

#define DIMC   1024
#define HEADS  16
#define HDIM   64
#define BATCH  4
#define NQL    1024
#define NKVL   1024
#define MROWS  (BATCH * NQL)   // 4096

// -------- scratch (no allocations allowed) --------
__device__ float g_q  [(size_t)MROWS * DIMC];
__device__ float g_k  [(size_t)MROWS * DIMC];
__device__ float g_v  [(size_t)MROWS * DIMC];
__device__ float g_ao [(size_t)MROWS * DIMC];
__device__ float g_xq [(size_t)MROWS * DIMC];
__device__ float g_xkv[(size_t)MROWS * DIMC];
__device__ float g_wq [(size_t)DIMC * DIMC];
__device__ float g_wk [(size_t)DIMC * DIMC];
__device__ float g_wv [(size_t)DIMC * DIMC];
__device__ float g_wo [(size_t)DIMC * DIMC];
__device__ float g_slr[(size_t)BATCH * NKVL];

// -------- helpers --------
__device__ __forceinline__ float f2tf32(float x) {
    uint32_t u;
    asm("cvt.rna.tf32.f32 %0, %1;" : "=r"(u) : "f"(x));
    return __uint_as_float(u);
}

__device__ __forceinline__ void mma_tf32(float c[4], const uint32_t a[4], const uint32_t b[2]) {
    asm volatile(
        "mma.sync.aligned.m16n8k8.row.col.f32.tf32.tf32.f32 "
        "{%0,%1,%2,%3},{%4,%5,%6,%7},{%8,%9},{%0,%1,%2,%3};\n"
        : "+f"(c[0]), "+f"(c[1]), "+f"(c[2]), "+f"(c[3])
        : "r"(a[0]), "r"(a[1]), "r"(a[2]), "r"(a[3]), "r"(b[0]), "r"(b[1]));
}

__device__ __forceinline__ uint32_t smem_u32(const void* p) {
    uint32_t a;
    asm("{ .reg .u64 t; cvta.to.shared.u64 t, %1; cvt.u32.u64 %0, t; }" : "=r"(a) : "l"(p));
    return a;
}

__device__ __forceinline__ void cp_a16(uint32_t dst, const float* src) {
    asm volatile("cp.async.cg.shared.global [%0], [%1], 16;" :: "r"(dst), "l"(src));
}

// ============================================================
// prep kernels
// ============================================================
__global__ void prep_slr(const float* __restrict__ rel, float* __restrict__ slr)
{
    const int i = blockIdx.x * 256 + threadIdx.x;
    slr[i] = logf(fmaxf(rel[i], 1e-6f));
}

// 4 independent float4 per thread (MLP=4): each block covers 1024 float4.
__global__ void conv_tf32(const float4* __restrict__ in, float4* __restrict__ out)
{
    const int base = blockIdx.x * 1024 + threadIdx.x;
    float4 v[4];
    #pragma unroll
    for (int j = 0; j < 4; j++) v[j] = in[base + j * 256];
    #pragma unroll
    for (int j = 0; j < 4; j++) {
        v[j].x = f2tf32(v[j].x); v[j].y = f2tf32(v[j].y);
        v[j].z = f2tf32(v[j].z); v[j].w = f2tf32(v[j].w);
        out[base + j * 256] = v[j];
    }
}

// ============================================================
// GEMM-NT:  C[m,n] = (sum_k A[m,k]*W[n,k] + bias[n]) * (GATE ? gate[m] : 1)
// Inputs pre-rounded tf32.  BM=BN=128, BK=32, 256 threads.
// 3-stage cp.async pipeline, ONE __syncthreads per k-tile, 2 CTAs/SM.
// ============================================================
#define BM 128
#define BN 128
#define BK 32
#define SAo 36         // padded smem row stride (floats); frag LDS conflict-free
#define NSTAGE 3
#define STG_A (BM * SAo)                 // 4608 floats per A stage
#define STG_B (BN * SAo)                 // 4608 floats per B stage
#define GEMM_SMEM (NSTAGE * (STG_A + STG_B) * 4)   // 110592 B

template<bool GATE, bool ROUND>
__global__ __launch_bounds__(256, 2)
void gemm_nt(const float* __restrict__ A, const float* __restrict__ W,
             const float* __restrict__ bias, const float* __restrict__ gate,
             float* __restrict__ C, int M, int N, int K)
{
    extern __shared__ float sm[];
    const uint32_t sbase = smem_u32(sm);

    const int tid  = threadIdx.x;
    const int wid  = tid >> 5;
    const int lane = tid & 31;
    const int g    = lane >> 2;
    const int t    = lane & 3;
    const int m0 = blockIdx.y * BM;
    const int n0 = blockIdx.x * BN;
    const int wm = (wid >> 2) * 64;
    const int wn = (wid & 3) * 32;

    const int lr = tid >> 3;              // 0..31
    const int lc = (tid & 7) * 4;         // 0..28

    float acc[4][4][4];
    #pragma unroll
    for (int i = 0; i < 4; i++)
        #pragma unroll
        for (int j = 0; j < 4; j++)
            #pragma unroll
            for (int c = 0; c < 4; c++) acc[i][j][c] = 0.f;

    const float* Ag = A + (size_t)(m0 + lr) * K + lc;
    const float* Bg = W + (size_t)(n0 + lr) * K + lc;

    auto issue_tile = [&](int kt, int s) {
        const int kc = kt * BK;
        #pragma unroll
        for (int i = 0; i < 4; i++) {
            const uint32_t da = sbase +
                (uint32_t)((s * STG_A + (lr + 32 * i) * SAo + lc) * 4);
            cp_a16(da, Ag + (size_t)(32 * i) * K + kc);
            const uint32_t db = sbase +
                (uint32_t)(((NSTAGE * STG_A) + s * STG_B + (lr + 32 * i) * SAo + lc) * 4);
            cp_a16(db, Bg + (size_t)(32 * i) * K + kc);
        }
        asm volatile("cp.async.commit_group;" ::: "memory");
    };

    issue_tile(0, 0);
    issue_tile(1, 1);

    const int KT = K / BK;
    for (int kt = 0; kt < KT; kt++) {
        const int s = kt % NSTAGE;
        // tile kt is the oldest group; one newer group may stay in flight
        if (kt + 1 < KT)
            asm volatile("cp.async.wait_group 1;" ::: "memory");
        else
            asm volatile("cp.async.wait_group 0;" ::: "memory");
        __syncthreads();   // publish tile kt; all warps done with stage (kt+2)%3

        if (kt + 2 < KT) issue_tile(kt + 2, (kt + 2) % NSTAGE);

        const float* Ab = sm + s * STG_A + wm * SAo;
        const float* Bb = sm + NSTAGE * STG_A + s * STG_B + wn * SAo;
        #pragma unroll
        for (int ks = 0; ks < 4; ks++) {
            const int kk = ks * 8;
            uint32_t af[4][4];
            #pragma unroll
            for (int mi = 0; mi < 4; mi++) {
                const float* p = Ab + (mi * 16 + g) * SAo + kk + t;
                af[mi][0] = __float_as_uint(p[0]);
                af[mi][1] = __float_as_uint(p[8 * SAo]);
                af[mi][2] = __float_as_uint(p[4]);
                af[mi][3] = __float_as_uint(p[8 * SAo + 4]);
            }
            uint32_t bf[4][2];
            #pragma unroll
            for (int ni = 0; ni < 4; ni++) {
                const float* p = Bb + (ni * 8 + g) * SAo + kk + t;
                bf[ni][0] = __float_as_uint(p[0]);
                bf[ni][1] = __float_as_uint(p[4]);
            }
            #pragma unroll
            for (int mi = 0; mi < 4; mi++)
                #pragma unroll
                for (int ni = 0; ni < 4; ni++)
                    mma_tf32(acc[mi][ni], af[mi], bf[ni]);
        }
    }

    // epilogue
    #pragma unroll
    for (int ni = 0; ni < 4; ni++) {
        const int cc = n0 + wn + ni * 8 + 2 * t;
        const float b0 = bias[cc];
        const float b1 = bias[cc + 1];
        #pragma unroll
        for (int mi = 0; mi < 4; mi++) {
            const int rr = m0 + wm + mi * 16 + g;
            float v0 = acc[mi][ni][0] + b0;
            float v1 = acc[mi][ni][1] + b1;
            float v2 = acc[mi][ni][2] + b0;
            float v3 = acc[mi][ni][3] + b1;
            if (GATE) {
                const float g0 = gate[rr];
                const float g1 = gate[rr + 8];
                v0 *= g0; v1 *= g0; v2 *= g1; v3 *= g1;
            }
            if (ROUND) {
                v0 = f2tf32(v0); v1 = f2tf32(v1);
                v2 = f2tf32(v2); v3 = f2tf32(v3);
            }
            *(float2*)(C + (size_t)rr * N + cc)       = make_float2(v0, v1);
            *(float2*)(C + (size_t)(rr + 8) * N + cc) = make_float2(v2, v3);
        }
    }
}

// ============================================================
// Flash attention (R9 proven): 128 threads (4 warps), warp = 32 q-rows.
// Q/K/V pre-rounded tf32.  K/V double-buffered frag-layout smem,
// register prefetch, 1 __syncthreads per KV tile.
// ============================================================
#define KF0_OFF   0
#define KF1_OFF   4096
#define VF0_OFF   8192
#define VF1_OFF   12288
#define PF_OFF    16384
#define SLR_OFF   24576
#define QS_OFF    8192
#define QS_STR    68
#define FATT_FLOATS 24704

__global__ __launch_bounds__(128, 2)
void flash_attn(const float* __restrict__ Q, const float* __restrict__ Kg,
                const float* __restrict__ V, const float* __restrict__ slrg,
                float* __restrict__ O)
{
    extern __shared__ float sm[];
    float* Pf  = sm + PF_OFF;
    float* Qs  = sm + QS_OFF;

    const int tid  = threadIdx.x;
    const int wid  = tid >> 5;
    const int lane = tid & 31;
    const int g    = lane >> 2;
    const int t    = lane & 3;
    const int q0   = blockIdx.x * 128;
    const int h    = blockIdx.y;
    const int b    = blockIdx.z;
    const int col0 = h * HDIM;
    const int wq   = wid * 32;

    // ---- stage Q tile (coalesced), extract frags to registers ----
    #pragma unroll
    for (int i = 0; i < 16; i++) {
        const int chunk = tid + 128 * i;
        const int row = chunk >> 4;
        const int c4  = (chunk & 15) * 4;
        float4 v = *(const float4*)(Q + (size_t)(b * NQL + q0 + row) * DIMC + col0 + c4);
        *(float4*)(Qs + row * QS_STR + c4) = v;
    }
    __syncthreads();

    uint32_t qf[2][8][4];
    #pragma unroll
    for (int mi = 0; mi < 2; mi++)
        #pragma unroll
        for (int ks = 0; ks < 8; ks++) {
            const float* p = Qs + (wq + mi * 16 + g) * QS_STR + ks * 8 + t;
            qf[mi][ks][0] = __float_as_uint(p[0]);
            qf[mi][ks][1] = __float_as_uint(p[8 * QS_STR]);
            qf[mi][ks][2] = __float_as_uint(p[4]);
            qf[mi][ks][3] = __float_as_uint(p[8 * QS_STR + 4]);
        }
    __syncthreads();   // Qs dead; smem free for KV buffers

    // loader geometry
    const int r0  = tid >> 4;          // 0..7
    const int c4  = (tid & 15) * 4;    // 0..60
    const int ksK = c4 >> 3;
    const int hkK = (c4 >> 2) & 1;
    const int nbV = c4 >> 3;
    const int g3b = c4 & 7;

    // prefetch tile 0
    float4 rk[8], rv[8];
    #pragma unroll
    for (int i = 0; i < 8; i++) {
        const int row = r0 + 8 * i;
        const size_t go = (size_t)(b * NKVL + row) * DIMC + col0 + c4;
        rk[i] = *(const float4*)(Kg + go);
        rv[i] = *(const float4*)(V  + go);
    }
    float slr_pre = (tid < 64) ? slrg[b * NKVL + tid] : 0.f;

    float mrow[2][2], lrow[2][2];
    #pragma unroll
    for (int mi = 0; mi < 2; mi++) { mrow[mi][0] = mrow[mi][1] = -1e30f; lrow[mi][0] = lrow[mi][1] = 0.f; }
    float oacc[2][8][4];
    #pragma unroll
    for (int mi = 0; mi < 2; mi++)
        #pragma unroll
        for (int nb = 0; nb < 8; nb++)
            #pragma unroll
            for (int c = 0; c < 4; c++) oacc[mi][nb][c] = 0.f;

    int buf = 0;
    for (int kt = 0; kt < NKVL / 64; kt++) {
        float* Kf = sm + (buf ? KF1_OFF : KF0_OFF);
        float* Vf = sm + (buf ? VF1_OFF : VF0_OFF);
        float* sl = sm + SLR_OFF + buf * 64;

        // ---- scatter prefetched tile into frag layouts ----
        #pragma unroll
        for (int i = 0; i < 8; i++) {
            const int row = r0 + 8 * i;
            const float kv[4] = {rk[i].x, rk[i].y, rk[i].z, rk[i].w};
            const float vv[4] = {rv[i].x, rv[i].y, rv[i].z, rv[i].w};
            {
                const int nb = row >> 3, g3 = row & 7;
                const int gs = g3 ^ (ksK >> 2);
                float* base = Kf + ((nb * 8 + ksK) * 32) * 2 + hkK;
                #pragma unroll
                for (int e = 0; e < 4; e++)
                    base[(gs * 4 + (e ^ ((nb ^ ksK) & 3))) * 2] = kv[e];
            }
            {
                const int ksV = row >> 3, tV = row & 3, hkV = (row >> 2) & 1;
                #pragma unroll
                for (int e = 0; e < 4; e++) {
                    const int gs = (g3b + e) ^ (ksV >> 2);
                    Vf[((nbV * 8 + ksV) * 32 + gs * 4 + (tV ^ ((nbV ^ ksV) & 3))) * 2 + hkV] = vv[e];
                }
            }
        }
        if (tid < 64) sl[tid] = slr_pre;
        __syncthreads();

        // ---- prefetch next tile K (hidden under QK) ----
        const int ktn = (kt + 1 < NKVL / 64) ? kt + 1 : kt;
        #pragma unroll
        for (int i = 0; i < 8; i++) {
            const int row = r0 + 8 * i;
            rk[i] = *(const float4*)(Kg + (size_t)(b * NKVL + ktn * 64 + row) * DIMC + col0 + c4);
        }
        if (tid < 64) slr_pre = slrg[b * NKVL + ktn * 64 + tid];

        // ---- per 16-row half: S = Q K^T, softmax, write P ----
        #pragma unroll
        for (int mi = 0; mi < 2; mi++) {
            float sacc[8][4];
            #pragma unroll
            for (int nb = 0; nb < 8; nb++)
                #pragma unroll
                for (int c = 0; c < 4; c++) sacc[nb][c] = 0.f;
            #pragma unroll
            for (int ks = 0; ks < 8; ks++) {
                #pragma unroll
                for (int nb = 0; nb < 8; nb++) {
                    const int slot = (g ^ (ks >> 2)) * 4 + (t ^ ((nb ^ ks) & 3));
                    float2 bv = *(const float2*)(Kf + ((nb * 8 + ks) * 32 + slot) * 2);
                    mma_tf32(sacc[nb], qf[mi][ks], (const uint32_t*)&bv);
                }
            }
            float mt0 = -1e30f, mt1 = -1e30f;
            #pragma unroll
            for (int nb = 0; nb < 8; nb++) {
                const int c = nb * 8 + 2 * t;
                const float l0 = sl[c], l1 = sl[c + 1];
                sacc[nb][0] = sacc[nb][0] * 0.125f + l0;
                sacc[nb][1] = sacc[nb][1] * 0.125f + l1;
                sacc[nb][2] = sacc[nb][2] * 0.125f + l0;
                sacc[nb][3] = sacc[nb][3] * 0.125f + l1;
                mt0 = fmaxf(mt0, fmaxf(sacc[nb][0], sacc[nb][1]));
                mt1 = fmaxf(mt1, fmaxf(sacc[nb][2], sacc[nb][3]));
            }
            mt0 = fmaxf(mt0, __shfl_xor_sync(0xffffffffu, mt0, 1));
            mt0 = fmaxf(mt0, __shfl_xor_sync(0xffffffffu, mt0, 2));
            mt1 = fmaxf(mt1, __shfl_xor_sync(0xffffffffu, mt1, 1));
            mt1 = fmaxf(mt1, __shfl_xor_sync(0xffffffffu, mt1, 2));
            const float mn0 = fmaxf(mrow[mi][0], mt0);
            const float mn1 = fmaxf(mrow[mi][1], mt1);

            const int t2 = (2 * t) & 3;
            const int hk = t >> 1;
            const int sg = (g >> 1) & 3;
            float* pw = Pf + ((wid * 2 + mi) * 8) * 128;
            float rs0 = 0.f, rs1 = 0.f;
            #pragma unroll
            for (int nb = 0; nb < 8; nb++) {
                const float p0 = __expf(sacc[nb][0] - mn0);
                const float p1 = __expf(sacc[nb][1] - mn0);
                const float p2 = __expf(sacc[nb][2] - mn1);
                const float p3 = __expf(sacc[nb][3] - mn1);
                rs0 += p0 + p1;
                rs1 += p2 + p3;
                float* base = pw + nb * 128;
                const int l0s = g * 4 + (t2 ^ sg);
                const int l1s = g * 4 + ((t2 + 1) ^ sg);
                *(float2*)(base + l0s * 4 + 2 * hk) = make_float2(f2tf32(p0), f2tf32(p2));
                *(float2*)(base + l1s * 4 + 2 * hk) = make_float2(f2tf32(p1), f2tf32(p3));
            }
            rs0 += __shfl_xor_sync(0xffffffffu, rs0, 1);
            rs0 += __shfl_xor_sync(0xffffffffu, rs0, 2);
            rs1 += __shfl_xor_sync(0xffffffffu, rs1, 1);
            rs1 += __shfl_xor_sync(0xffffffffu, rs1, 2);

            const float al0 = __expf(mrow[mi][0] - mn0);
            const float al1 = __expf(mrow[mi][1] - mn1);
            lrow[mi][0] = lrow[mi][0] * al0 + rs0;
            lrow[mi][1] = lrow[mi][1] * al1 + rs1;
            mrow[mi][0] = mn0; mrow[mi][1] = mn1;
            #pragma unroll
            for (int nb = 0; nb < 8; nb++) {
                oacc[mi][nb][0] *= al0; oacc[mi][nb][1] *= al0;
                oacc[mi][nb][2] *= al1; oacc[mi][nb][3] *= al1;
            }
        }
        __syncwarp();   // Pf is per-warp private

        // ---- prefetch next tile V (hidden under PV) ----
        #pragma unroll
        for (int i = 0; i < 8; i++) {
            const int row = r0 + 8 * i;
            rv[i] = *(const float4*)(V + (size_t)(b * NKVL + ktn * 64 + row) * DIMC + col0 + c4);
        }

        // ---- O += P V ----
        #pragma unroll
        for (int ks = 0; ks < 8; ks++) {
            const int pslot = g * 4 + (t ^ ((g >> 1) & 3));
            float4 a0 = *(const float4*)(Pf + ((wid * 2 + 0) * 8 + ks) * 128 + pslot * 4);
            float4 a1 = *(const float4*)(Pf + ((wid * 2 + 1) * 8 + ks) * 128 + pslot * 4);
            #pragma unroll
            for (int nb = 0; nb < 8; nb++) {
                const int slot = (g ^ (ks >> 2)) * 4 + (t ^ ((nb ^ ks) & 3));
                float2 bv = *(const float2*)(Vf + ((nb * 8 + ks) * 32 + slot) * 2);
                mma_tf32(oacc[0][nb], (const uint32_t*)&a0, (const uint32_t*)&bv);
                mma_tf32(oacc[1][nb], (const uint32_t*)&a1, (const uint32_t*)&bv);
            }
        }
        buf ^= 1;
    }

    // ---- epilogue (round output: feeds final GEMM) ----
    #pragma unroll
    for (int mi = 0; mi < 2; mi++) {
        const float il0 = 1.f / lrow[mi][0];
        const float il1 = 1.f / lrow[mi][1];
        const size_t orow = (size_t)(b * NQL + q0 + wq + mi * 16 + g);
        #pragma unroll
        for (int nb = 0; nb < 8; nb++) {
            const int c = col0 + nb * 8 + 2 * t;
            *(float2*)(O + orow * DIMC + c) =
                make_float2(f2tf32(oacc[mi][nb][0] * il0), f2tf32(oacc[mi][nb][1] * il0));
            *(float2*)(O + (orow + 8) * DIMC + c) =
                make_float2(f2tf32(oacc[mi][nb][2] * il1), f2tf32(oacc[mi][nb][3] * il1));
        }
    }
}

// ============================================================
// Launch
// ============================================================
extern "C" void kernel_launch(void* const* d_in, const int* in_sizes, int n_in,
                              void* d_out, int out_size)
{
    (void)in_sizes; (void)n_in; (void)out_size;
    const float* qf  = (const float*)d_in[0];
    const float* kvf = (const float*)d_in[1];
    const float* rel = (const float*)d_in[2];
    const float* Wq  = (const float*)d_in[3];
    const float* bq  = (const float*)d_in[4];
    const float* Wk  = (const float*)d_in[5];
    const float* bk  = (const float*)d_in[6];
    const float* Wv  = (const float*)d_in[7];
    const float* bv  = (const float*)d_in[8];
    const float* Wo  = (const float*)d_in[9];
    const float* bo  = (const float*)d_in[10];
    float* out = (float*)d_out;

    float *pq, *pk, *pv, *pao, *pxq, *pxkv, *pwq, *pwk, *pwv, *pwo, *pslr;
    cudaGetSymbolAddress((void**)&pq,   g_q);
    cudaGetSymbolAddress((void**)&pk,   g_k);
    cudaGetSymbolAddress((void**)&pv,   g_v);
    cudaGetSymbolAddress((void**)&pao,  g_ao);
    cudaGetSymbolAddress((void**)&pxq,  g_xq);
    cudaGetSymbolAddress((void**)&pxkv, g_xkv);
    cudaGetSymbolAddress((void**)&pwq,  g_wq);
    cudaGetSymbolAddress((void**)&pwk,  g_wk);
    cudaGetSymbolAddress((void**)&pwv,  g_wv);
    cudaGetSymbolAddress((void**)&pwo,  g_wo);
    cudaGetSymbolAddress((void**)&pslr, g_slr);

    const int flash_smem = FATT_FLOATS * 4;   // 98816 B

    cudaFuncSetAttribute(gemm_nt<false, true>,
                         cudaFuncAttributeMaxDynamicSharedMemorySize, GEMM_SMEM);
    cudaFuncSetAttribute(gemm_nt<true, true>,
                         cudaFuncAttributeMaxDynamicSharedMemorySize, GEMM_SMEM);
    cudaFuncSetAttribute(gemm_nt<false, false>,
                         cudaFuncAttributeMaxDynamicSharedMemorySize, GEMM_SMEM);
    cudaFuncSetAttribute(flash_attn,
                         cudaFuncAttributeMaxDynamicSharedMemorySize, flash_smem);

    // ---- prep: tf32 pre-rounding (ILP=4 float4/thread) + log-reliability ----
    prep_slr<<<BATCH * NKVL / 256, 256>>>(rel, pslr);
    conv_tf32<<<(MROWS * DIMC) / 4 / 1024, 256>>>((const float4*)qf,  (float4*)pxq);
    conv_tf32<<<(MROWS * DIMC) / 4 / 1024, 256>>>((const float4*)kvf, (float4*)pxkv);
    conv_tf32<<<(DIMC * DIMC) / 4 / 1024, 256>>>((const float4*)Wq, (float4*)pwq);
    conv_tf32<<<(DIMC * DIMC) / 4 / 1024, 256>>>((const float4*)Wk, (float4*)pwk);
    conv_tf32<<<(DIMC * DIMC) / 4 / 1024, 256>>>((const float4*)Wv, (float4*)pwv);
    conv_tf32<<<(DIMC * DIMC) / 4 / 1024, 256>>>((const float4*)Wo, (float4*)pwo);

    dim3 gg(DIMC / BN, MROWS / BM);   // (8, 32)
    gemm_nt<false, true><<<gg, 256, GEMM_SMEM>>>(pxq,  pwq, bq, nullptr, pq, MROWS, DIMC, DIMC);
    gemm_nt<true,  true><<<gg, 256, GEMM_SMEM>>>(pxkv, pwk, bk, rel,     pk, MROWS, DIMC, DIMC);
    gemm_nt<true,  true><<<gg, 256, GEMM_SMEM>>>(pxkv, pwv, bv, rel,     pv, MROWS, DIMC, DIMC);

    flash_attn<<<dim3(NQL / 128, HEADS, BATCH), 128, flash_smem>>>(pq, pk, pv, pslr, pao);

    gemm_nt<false, false><<<gg, 256, GEMM_SMEM>>>(pao, pwo, bo, nullptr, out, MROWS, DIMC, DIMC);
}

// round 15
// speedup vs baseline: 1.1809x; 1.1809x over previous
#include <cuda_runtime.h>
#include <math.h>
#include <stdint.h>

// ============================================================
// ReliabilityGatedCrossAttention  (B=4, N=1024, DIM=1024, H=16, d=64)
// All matmuls: mma.sync m16n8k8 tf32.  tf32 rounding at producers.
// GEMM: R9 proven 2-stage cp.async.  Flash: cp.async row-major K/V
// tiles (no scatter), hoisted K-frags, LDG slr.
// ============================================================

#define DIMC   1024
#define HEADS  16
#define HDIM   64
#define BATCH  4
#define NQL    1024
#define NKVL   1024
#define MROWS  (BATCH * NQL)   // 4096

// -------- scratch (no allocations allowed) --------
__device__ float g_q  [(size_t)MROWS * DIMC];
__device__ float g_k  [(size_t)MROWS * DIMC];
__device__ float g_v  [(size_t)MROWS * DIMC];
__device__ float g_ao [(size_t)MROWS * DIMC];
__device__ float g_xq [(size_t)MROWS * DIMC];
__device__ float g_xkv[(size_t)MROWS * DIMC];
__device__ float g_wq [(size_t)DIMC * DIMC];
__device__ float g_wk [(size_t)DIMC * DIMC];
__device__ float g_wv [(size_t)DIMC * DIMC];
__device__ float g_wo [(size_t)DIMC * DIMC];
__device__ float g_slr[(size_t)BATCH * NKVL];

// -------- helpers --------
__device__ __forceinline__ float f2tf32(float x) {
    uint32_t u;
    asm("cvt.rna.tf32.f32 %0, %1;" : "=r"(u) : "f"(x));
    return __uint_as_float(u);
}

__device__ __forceinline__ void mma_tf32(float c[4], const uint32_t a[4], const uint32_t b[2]) {
    asm volatile(
        "mma.sync.aligned.m16n8k8.row.col.f32.tf32.tf32.f32 "
        "{%0,%1,%2,%3},{%4,%5,%6,%7},{%8,%9},{%0,%1,%2,%3};\n"
        : "+f"(c[0]), "+f"(c[1]), "+f"(c[2]), "+f"(c[3])
        : "r"(a[0]), "r"(a[1]), "r"(a[2]), "r"(a[3]), "r"(b[0]), "r"(b[1]));
}

__device__ __forceinline__ uint32_t smem_u32(const void* p) {
    uint32_t a;
    asm("{ .reg .u64 t; cvta.to.shared.u64 t, %1; cvt.u32.u64 %0, t; }" : "=r"(a) : "l"(p));
    return a;
}

__device__ __forceinline__ void cp_a16(uint32_t dst, const float* src) {
    asm volatile("cp.async.cg.shared.global [%0], [%1], 16;" :: "r"(dst), "l"(src));
}

// ============================================================
// prep kernels (R9 proven shapes)
// ============================================================
__global__ void prep_slr(const float* __restrict__ rel, float* __restrict__ slr)
{
    const int i = blockIdx.x * 256 + threadIdx.x;
    slr[i] = logf(fmaxf(rel[i], 1e-6f));
}

__global__ void conv_tf32(const float* __restrict__ in, float* __restrict__ out)
{
    const int i = blockIdx.x * 256 + threadIdx.x;
    float4 v = ((const float4*)in)[i];
    v.x = f2tf32(v.x); v.y = f2tf32(v.y); v.z = f2tf32(v.z); v.w = f2tf32(v.w);
    ((float4*)out)[i] = v;
}

// ============================================================
// GEMM-NT (R9 proven):  C = (A W^T + bias) * gate?
// BM=BN=128, BK=32, 256 threads, 2-stage cp.async, 2 CTAs/SM.
// ============================================================
#define BM 128
#define BN 128
#define BK 32
#define SAo 36   // padded smem row stride (floats); frag LDS conflict-free

template<bool GATE, bool ROUND>
__global__ __launch_bounds__(256, 2)
void gemm_nt(const float* __restrict__ A, const float* __restrict__ W,
             const float* __restrict__ bias, const float* __restrict__ gate,
             float* __restrict__ C, int M, int N, int K)
{
    extern __shared__ float sm[];
    const uint32_t sbase = smem_u32(sm);

    const int tid  = threadIdx.x;
    const int wid  = tid >> 5;
    const int lane = tid & 31;
    const int g    = lane >> 2;
    const int t    = lane & 3;
    const int m0 = blockIdx.y * BM;
    const int n0 = blockIdx.x * BN;
    const int wm = (wid >> 2) * 64;
    const int wn = (wid & 3) * 32;

    const int lr = tid >> 3;              // 0..31
    const int lc = (tid & 7) * 4;         // 0..28

    float acc[4][4][4];
    #pragma unroll
    for (int i = 0; i < 4; i++)
        #pragma unroll
        for (int j = 0; j < 4; j++)
            #pragma unroll
            for (int c = 0; c < 4; c++) acc[i][j][c] = 0.f;

    const float* Ag = A + (size_t)(m0 + lr) * K + lc;
    const float* Bg = W + (size_t)(n0 + lr) * K + lc;

    auto issue_tile = [&](int kt, int s) {
        const int kc = kt * BK;
        #pragma unroll
        for (int i = 0; i < 4; i++) {
            const uint32_t da = sbase +
                (uint32_t)((s * BM * SAo + (lr + 32 * i) * SAo + lc) * 4);
            cp_a16(da, Ag + (size_t)(32 * i) * K + kc);
            const uint32_t db = sbase +
                (uint32_t)(((2 * BM * SAo) + s * BN * SAo + (lr + 32 * i) * SAo + lc) * 4);
            cp_a16(db, Bg + (size_t)(32 * i) * K + kc);
        }
        asm volatile("cp.async.commit_group;" ::: "memory");
    };

    issue_tile(0, 0);

    const int KT = K / BK;
    for (int kt = 0; kt < KT; kt++) {
        const int s = kt & 1;
        if (kt + 1 < KT) {
            issue_tile(kt + 1, s ^ 1);
            asm volatile("cp.async.wait_group 1;" ::: "memory");
        } else {
            asm volatile("cp.async.wait_group 0;" ::: "memory");
        }
        __syncthreads();

        const float* Ab = sm + s * BM * SAo + wm * SAo;
        const float* Bb = sm + 2 * BM * SAo + s * BN * SAo + wn * SAo;
        #pragma unroll
        for (int ks = 0; ks < 4; ks++) {
            const int kk = ks * 8;
            uint32_t af[4][4];
            #pragma unroll
            for (int mi = 0; mi < 4; mi++) {
                const float* p = Ab + (mi * 16 + g) * SAo + kk + t;
                af[mi][0] = __float_as_uint(p[0]);
                af[mi][1] = __float_as_uint(p[8 * SAo]);
                af[mi][2] = __float_as_uint(p[4]);
                af[mi][3] = __float_as_uint(p[8 * SAo + 4]);
            }
            uint32_t bf[4][2];
            #pragma unroll
            for (int ni = 0; ni < 4; ni++) {
                const float* p = Bb + (ni * 8 + g) * SAo + kk + t;
                bf[ni][0] = __float_as_uint(p[0]);
                bf[ni][1] = __float_as_uint(p[4]);
            }
            #pragma unroll
            for (int mi = 0; mi < 4; mi++)
                #pragma unroll
                for (int ni = 0; ni < 4; ni++)
                    mma_tf32(acc[mi][ni], af[mi], bf[ni]);
        }
        __syncthreads();
    }

    // epilogue
    #pragma unroll
    for (int ni = 0; ni < 4; ni++) {
        const int cc = n0 + wn + ni * 8 + 2 * t;
        const float b0 = bias[cc];
        const float b1 = bias[cc + 1];
        #pragma unroll
        for (int mi = 0; mi < 4; mi++) {
            const int rr = m0 + wm + mi * 16 + g;
            float v0 = acc[mi][ni][0] + b0;
            float v1 = acc[mi][ni][1] + b1;
            float v2 = acc[mi][ni][2] + b0;
            float v3 = acc[mi][ni][3] + b1;
            if (GATE) {
                const float g0 = gate[rr];
                const float g1 = gate[rr + 8];
                v0 *= g0; v1 *= g0; v2 *= g1; v3 *= g1;
            }
            if (ROUND) {
                v0 = f2tf32(v0); v1 = f2tf32(v1);
                v2 = f2tf32(v2); v3 = f2tf32(v3);
            }
            *(float2*)(C + (size_t)rr * N + cc)       = make_float2(v0, v1);
            *(float2*)(C + (size_t)(rr + 8) * N + cc) = make_float2(v2, v3);
        }
    }
}

// ============================================================
// Flash attention: 128 threads (4 warps), warp = 32 q-rows.
// K/V loaded via cp.async into row-major smem tiles (double-buffered):
//   Kt[kv][d]: stride 68  -> frag LDS bank = g*4+t  (conflict-free)
//   Vt[kv][d]: stride 72  -> frag LDS bank = t*8+g  (conflict-free)
// No scatter STS, no prefetch registers.  slr read via LDG (cached).
// Pf: per-warp P relayout buffer (C-frag -> A-frag), as before.
// ============================================================
#define KS_STR  68
#define VS_STR  72
#define K0_OFF  0
#define K1_OFF  4352              // 64*68
#define V0_OFF  8704
#define V1_OFF  13312             // + 64*72
#define PF_OFF  17920
#define QS_OFF  0                 // alias over K/V buffers (dead after prologue)
#define QS_STR  68
#define FATT_FLOATS 26112         // 17920 + 8192
#define FATT_SMEM   (FATT_FLOATS * 4)   // 104448 B

__global__ __launch_bounds__(128, 2)
void flash_attn(const float* __restrict__ Q, const float* __restrict__ Kg,
                const float* __restrict__ V, const float* __restrict__ slrg,
                float* __restrict__ O)
{
    extern __shared__ float sm[];
    float* Pf = sm + PF_OFF;
    float* Qs = sm + QS_OFF;
    const uint32_t sbase = smem_u32(sm);

    const int tid  = threadIdx.x;
    const int wid  = tid >> 5;
    const int lane = tid & 31;
    const int g    = lane >> 2;
    const int t    = lane & 3;
    const int q0   = blockIdx.x * 128;
    const int h    = blockIdx.y;
    const int b    = blockIdx.z;
    const int col0 = h * HDIM;
    const int wq   = wid * 32;

    // ---- stage Q tile (coalesced), extract frags to registers ----
    #pragma unroll
    for (int i = 0; i < 16; i++) {
        const int chunk = tid + 128 * i;
        const int row = chunk >> 4;
        const int c4q = (chunk & 15) * 4;
        float4 v = *(const float4*)(Q + (size_t)(b * NQL + q0 + row) * DIMC + col0 + c4q);
        *(float4*)(Qs + row * QS_STR + c4q) = v;
    }
    __syncthreads();

    uint32_t qf[2][8][4];
    #pragma unroll
    for (int mi = 0; mi < 2; mi++)
        #pragma unroll
        for (int ks = 0; ks < 8; ks++) {
            const float* p = Qs + (wq + mi * 16 + g) * QS_STR + ks * 8 + t;
            qf[mi][ks][0] = __float_as_uint(p[0]);
            qf[mi][ks][1] = __float_as_uint(p[8 * QS_STR]);
            qf[mi][ks][2] = __float_as_uint(p[4]);
            qf[mi][ks][3] = __float_as_uint(p[8 * QS_STR + 4]);
        }
    __syncthreads();   // Qs dead; smem free for K/V buffers

    // ---- cp.async loader geometry: thread covers 8 rows x 16B ----
    const int r0 = tid >> 4;          // 0..7
    const int c4 = (tid & 15) * 4;    // 0..60
    const float* Kbase = Kg + (size_t)b * NKVL * DIMC + col0 + c4;
    const float* Vbase = V  + (size_t)b * NKVL * DIMC + col0 + c4;

    auto issue_kv = [&](int kt, int bu) {
        const uint32_t ko = sbase + (uint32_t)(((bu ? K1_OFF : K0_OFF)) * 4);
        const uint32_t vo = sbase + (uint32_t)(((bu ? V1_OFF : V0_OFF)) * 4);
        #pragma unroll
        for (int i = 0; i < 8; i++) {
            const int row = r0 + 8 * i;
            const size_t go = (size_t)(kt * 64 + row) * DIMC;
            cp_a16(ko + (uint32_t)((row * KS_STR + c4) * 4), Kbase + go);
            cp_a16(vo + (uint32_t)((row * VS_STR + c4) * 4), Vbase + go);
        }
        asm volatile("cp.async.commit_group;" ::: "memory");
    };

    issue_kv(0, 0);

    float mrow[2][2], lrow[2][2];
    #pragma unroll
    for (int mi = 0; mi < 2; mi++) { mrow[mi][0] = mrow[mi][1] = -1e30f; lrow[mi][0] = lrow[mi][1] = 0.f; }
    float oacc[2][8][4];
    #pragma unroll
    for (int mi = 0; mi < 2; mi++)
        #pragma unroll
        for (int nb = 0; nb < 8; nb++)
            #pragma unroll
            for (int c = 0; c < 4; c++) oacc[mi][nb][c] = 0.f;

    const float* slr_b = slrg + b * NKVL;

    int buf = 0;
    const int KT = NKVL / 64;
    for (int kt = 0; kt < KT; kt++) {
        asm volatile("cp.async.wait_group 0;" ::: "memory");
        __syncthreads();                       // tile kt visible; prev buffers free
        if (kt + 1 < KT) issue_kv(kt + 1, buf ^ 1);

        const float* Kt = sm + (buf ? K1_OFF : K0_OFF);
        const float* Vt = sm + (buf ? V1_OFF : V0_OFF);

        // ---- S = Q K^T  (K-frags loaded once, shared by both halves) ----
        float sacc[2][8][4];
        #pragma unroll
        for (int mi = 0; mi < 2; mi++)
            #pragma unroll
            for (int nb = 0; nb < 8; nb++)
                #pragma unroll
                for (int c = 0; c < 4; c++) sacc[mi][nb][c] = 0.f;
        #pragma unroll
        for (int ks = 0; ks < 8; ks++) {
            uint32_t bf[8][2];
            #pragma unroll
            for (int nb = 0; nb < 8; nb++) {
                const float* p = Kt + (nb * 8 + g) * KS_STR + ks * 8 + t;
                bf[nb][0] = __float_as_uint(p[0]);
                bf[nb][1] = __float_as_uint(p[4]);
            }
            #pragma unroll
            for (int nb = 0; nb < 8; nb++) {
                mma_tf32(sacc[0][nb], qf[0][ks], bf[nb]);
                mma_tf32(sacc[1][nb], qf[1][ks], bf[nb]);
            }
        }

        // ---- softmax per 16-row half; write P in PV A-frag layout ----
        const int slr0 = kt * 64 + 2 * t;
        #pragma unroll
        for (int mi = 0; mi < 2; mi++) {
            float mt0 = -1e30f, mt1 = -1e30f;
            #pragma unroll
            for (int nb = 0; nb < 8; nb++) {
                const float2 l2 = *(const float2*)(slr_b + slr0 + nb * 8);
                sacc[mi][nb][0] = sacc[mi][nb][0] * 0.125f + l2.x;
                sacc[mi][nb][1] = sacc[mi][nb][1] * 0.125f + l2.y;
                sacc[mi][nb][2] = sacc[mi][nb][2] * 0.125f + l2.x;
                sacc[mi][nb][3] = sacc[mi][nb][3] * 0.125f + l2.y;
                mt0 = fmaxf(mt0, fmaxf(sacc[mi][nb][0], sacc[mi][nb][1]));
                mt1 = fmaxf(mt1, fmaxf(sacc[mi][nb][2], sacc[mi][nb][3]));
            }
            mt0 = fmaxf(mt0, __shfl_xor_sync(0xffffffffu, mt0, 1));
            mt0 = fmaxf(mt0, __shfl_xor_sync(0xffffffffu, mt0, 2));
            mt1 = fmaxf(mt1, __shfl_xor_sync(0xffffffffu, mt1, 1));
            mt1 = fmaxf(mt1, __shfl_xor_sync(0xffffffffu, mt1, 2));
            const float mn0 = fmaxf(mrow[mi][0], mt0);
            const float mn1 = fmaxf(mrow[mi][1], mt1);

            const int t2 = (2 * t) & 3;
            const int hk = t >> 1;
            const int sg = (g >> 1) & 3;
            float* pw = Pf + ((wid * 2 + mi) * 8) * 128;
            float rs0 = 0.f, rs1 = 0.f;
            #pragma unroll
            for (int nb = 0; nb < 8; nb++) {
                const float p0 = __expf(sacc[mi][nb][0] - mn0);
                const float p1 = __expf(sacc[mi][nb][1] - mn0);
                const float p2 = __expf(sacc[mi][nb][2] - mn1);
                const float p3 = __expf(sacc[mi][nb][3] - mn1);
                rs0 += p0 + p1;
                rs1 += p2 + p3;
                float* base = pw + nb * 128;
                const int l0s = g * 4 + (t2 ^ sg);
                const int l1s = g * 4 + ((t2 + 1) ^ sg);
                *(float2*)(base + l0s * 4 + 2 * hk) = make_float2(f2tf32(p0), f2tf32(p2));
                *(float2*)(base + l1s * 4 + 2 * hk) = make_float2(f2tf32(p1), f2tf32(p3));
            }
            rs0 += __shfl_xor_sync(0xffffffffu, rs0, 1);
            rs0 += __shfl_xor_sync(0xffffffffu, rs0, 2);
            rs1 += __shfl_xor_sync(0xffffffffu, rs1, 1);
            rs1 += __shfl_xor_sync(0xffffffffu, rs1, 2);

            const float al0 = __expf(mrow[mi][0] - mn0);
            const float al1 = __expf(mrow[mi][1] - mn1);
            lrow[mi][0] = lrow[mi][0] * al0 + rs0;
            lrow[mi][1] = lrow[mi][1] * al1 + rs1;
            mrow[mi][0] = mn0; mrow[mi][1] = mn1;
            #pragma unroll
            for (int nb = 0; nb < 8; nb++) {
                oacc[mi][nb][0] *= al0; oacc[mi][nb][1] *= al0;
                oacc[mi][nb][2] *= al1; oacc[mi][nb][3] *= al1;
            }
        }
        __syncwarp();   // Pf is per-warp private

        // ---- O += P V  (V-frags from row-major Vt, loaded once per ks) ----
        #pragma unroll
        for (int ks = 0; ks < 8; ks++) {
            uint32_t vf[8][2];
            #pragma unroll
            for (int nb = 0; nb < 8; nb++) {
                const float* p = Vt + (ks * 8 + t) * VS_STR + nb * 8 + g;
                vf[nb][0] = __float_as_uint(p[0]);
                vf[nb][1] = __float_as_uint(p[4 * VS_STR]);
            }
            const int pslot = g * 4 + (t ^ ((g >> 1) & 3));
            float4 a0 = *(const float4*)(Pf + ((wid * 2 + 0) * 8 + ks) * 128 + pslot * 4);
            float4 a1 = *(const float4*)(Pf + ((wid * 2 + 1) * 8 + ks) * 128 + pslot * 4);
            #pragma unroll
            for (int nb = 0; nb < 8; nb++) {
                mma_tf32(oacc[0][nb], (const uint32_t*)&a0, vf[nb]);
                mma_tf32(oacc[1][nb], (const uint32_t*)&a1, vf[nb]);
            }
        }
        buf ^= 1;
    }

    // ---- epilogue (round output: feeds final GEMM) ----
    #pragma unroll
    for (int mi = 0; mi < 2; mi++) {
        const float il0 = 1.f / lrow[mi][0];
        const float il1 = 1.f / lrow[mi][1];
        const size_t orow = (size_t)(b * NQL + q0 + wq + mi * 16 + g);
        #pragma unroll
        for (int nb = 0; nb < 8; nb++) {
            const int c = col0 + nb * 8 + 2 * t;
            *(float2*)(O + orow * DIMC + c) =
                make_float2(f2tf32(oacc[mi][nb][0] * il0), f2tf32(oacc[mi][nb][1] * il0));
            *(float2*)(O + (orow + 8) * DIMC + c) =
                make_float2(f2tf32(oacc[mi][nb][2] * il1), f2tf32(oacc[mi][nb][3] * il1));
        }
    }
}

// ============================================================
// Launch
// ============================================================
extern "C" void kernel_launch(void* const* d_in, const int* in_sizes, int n_in,
                              void* d_out, int out_size)
{
    (void)in_sizes; (void)n_in; (void)out_size;
    const float* qf  = (const float*)d_in[0];
    const float* kvf = (const float*)d_in[1];
    const float* rel = (const float*)d_in[2];
    const float* Wq  = (const float*)d_in[3];
    const float* bq  = (const float*)d_in[4];
    const float* Wk  = (const float*)d_in[5];
    const float* bk  = (const float*)d_in[6];
    const float* Wv  = (const float*)d_in[7];
    const float* bv  = (const float*)d_in[8];
    const float* Wo  = (const float*)d_in[9];
    const float* bo  = (const float*)d_in[10];
    float* out = (float*)d_out;

    float *pq, *pk, *pv, *pao, *pxq, *pxkv, *pwq, *pwk, *pwv, *pwo, *pslr;
    cudaGetSymbolAddress((void**)&pq,   g_q);
    cudaGetSymbolAddress((void**)&pk,   g_k);
    cudaGetSymbolAddress((void**)&pv,   g_v);
    cudaGetSymbolAddress((void**)&pao,  g_ao);
    cudaGetSymbolAddress((void**)&pxq,  g_xq);
    cudaGetSymbolAddress((void**)&pxkv, g_xkv);
    cudaGetSymbolAddress((void**)&pwq,  g_wq);
    cudaGetSymbolAddress((void**)&pwk,  g_wk);
    cudaGetSymbolAddress((void**)&pwv,  g_wv);
    cudaGetSymbolAddress((void**)&pwo,  g_wo);
    cudaGetSymbolAddress((void**)&pslr, g_slr);

    const int gemm_smem = (int)(2 * BM * SAo + 2 * BN * SAo) * 4;   // 73728 B

    cudaFuncSetAttribute(gemm_nt<false, true>,
                         cudaFuncAttributeMaxDynamicSharedMemorySize, gemm_smem);
    cudaFuncSetAttribute(gemm_nt<true, true>,
                         cudaFuncAttributeMaxDynamicSharedMemorySize, gemm_smem);
    cudaFuncSetAttribute(gemm_nt<false, false>,
                         cudaFuncAttributeMaxDynamicSharedMemorySize, gemm_smem);
    cudaFuncSetAttribute(flash_attn,
                         cudaFuncAttributeMaxDynamicSharedMemorySize, FATT_SMEM);

    // ---- prep: tf32 pre-rounding + log-reliability ----
    prep_slr<<<BATCH * NKVL / 256, 256>>>(rel, pslr);
    conv_tf32<<<(MROWS * DIMC) / 4 / 256, 256>>>(qf,  pxq);
    conv_tf32<<<(MROWS * DIMC) / 4 / 256, 256>>>(kvf, pxkv);
    conv_tf32<<<(DIMC * DIMC) / 4 / 256, 256>>>(Wq, pwq);
    conv_tf32<<<(DIMC * DIMC) / 4 / 256, 256>>>(Wk, pwk);
    conv_tf32<<<(DIMC * DIMC) / 4 / 256, 256>>>(Wv, pwv);
    conv_tf32<<<(DIMC * DIMC) / 4 / 256, 256>>>(Wo, pwo);

    dim3 gg(DIMC / BN, MROWS / BM);   // (8, 32)
    gemm_nt<false, true><<<gg, 256, gemm_smem>>>(pxq,  pwq, bq, nullptr, pq, MROWS, DIMC, DIMC);
    gemm_nt<true,  true><<<gg, 256, gemm_smem>>>(pxkv, pwk, bk, rel,     pk, MROWS, DIMC, DIMC);
    gemm_nt<true,  true><<<gg, 256, gemm_smem>>>(pxkv, pwv, bv, rel,     pv, MROWS, DIMC, DIMC);

    flash_attn<<<dim3(NQL / 128, HEADS, BATCH), 128, FATT_SMEM>>>(pq, pk, pv, pslr, pao);

    gemm_nt<false, false><<<gg, 256, gemm_smem>>>(pao, pwo, bo, nullptr, out, MROWS, DIMC, DIMC);
}

// round 16
// speedup vs baseline: 1.2212x; 1.0342x over previous
#include <cuda_runtime.h>
#include <math.h>
#include <stdint.h>

// ============================================================
// ReliabilityGatedCrossAttention  (B=4, N=1024, DIM=1024, H=16, d=64)
// All matmuls: mma.sync m16n8k8 tf32.  tf32 rounding at producers:
// ONE fused grid-stride prep kernel (inputs+weights+log-reliability).
// GEMM: R9 proven 2-stage cp.async.  Flash: R15 proven row-major
// cp.async K/V tiles, hoisted K-frags, LDG slr.
// ============================================================

#define DIMC   1024
#define HEADS  16
#define HDIM   64
#define BATCH  4
#define NQL    1024
#define NKVL   1024
#define MROWS  (BATCH * NQL)   // 4096

// -------- scratch (no allocations allowed) --------
__device__ float g_q  [(size_t)MROWS * DIMC];
__device__ float g_k  [(size_t)MROWS * DIMC];
__device__ float g_v  [(size_t)MROWS * DIMC];
__device__ float g_ao [(size_t)MROWS * DIMC];
__device__ float g_xq [(size_t)MROWS * DIMC];
__device__ float g_xkv[(size_t)MROWS * DIMC];
__device__ float g_wq [(size_t)DIMC * DIMC];
__device__ float g_wk [(size_t)DIMC * DIMC];
__device__ float g_wv [(size_t)DIMC * DIMC];
__device__ float g_wo [(size_t)DIMC * DIMC];
__device__ float g_slr[(size_t)BATCH * NKVL];

// -------- helpers --------
__device__ __forceinline__ float f2tf32(float x) {
    uint32_t u;
    asm("cvt.rna.tf32.f32 %0, %1;" : "=r"(u) : "f"(x));
    return __uint_as_float(u);
}

__device__ __forceinline__ void mma_tf32(float c[4], const uint32_t a[4], const uint32_t b[2]) {
    asm volatile(
        "mma.sync.aligned.m16n8k8.row.col.f32.tf32.tf32.f32 "
        "{%0,%1,%2,%3},{%4,%5,%6,%7},{%8,%9},{%0,%1,%2,%3};\n"
        : "+f"(c[0]), "+f"(c[1]), "+f"(c[2]), "+f"(c[3])
        : "r"(a[0]), "r"(a[1]), "r"(a[2]), "r"(a[3]), "r"(b[0]), "r"(b[1]));
}

__device__ __forceinline__ uint32_t smem_u32(const void* p) {
    uint32_t a;
    asm("{ .reg .u64 t; cvta.to.shared.u64 t, %1; cvt.u32.u64 %0, t; }" : "=r"(a) : "l"(p));
    return a;
}

__device__ __forceinline__ void cp_a16(uint32_t dst, const float* src) {
    asm volatile("cp.async.cg.shared.global [%0], [%1], 16;" :: "r"(dst), "l"(src));
}

// ============================================================
// Fused prep: tf32-round xq, xkv, Wq, Wk, Wv, Wo  +  slr = log(clip(rel)).
// One launch.  Region decoded from blockIdx; each block covers 1024
// contiguous float4 (256 thr x 4, stride 256).  All region sizes are
// multiples of 1024 float4, so a block never straddles regions.
// ============================================================
#define XQ4  (MROWS * DIMC / 4)    // 1048576 float4
#define W4   (DIMC * DIMC / 4)     // 262144 float4
#define NB_X (XQ4 / 1024)          // 1024 blocks per X region
#define NB_W (W4 / 1024)           // 256 blocks per W region
#define PREP_BLOCKS (2 * NB_X + 4 * NB_W)   // 3072

__global__ __launch_bounds__(256)
void prep_all(const float4* __restrict__ xq_in,  float4* __restrict__ xq_out,
              const float4* __restrict__ xkv_in, float4* __restrict__ xkv_out,
              const float4* __restrict__ wq_in,  float4* __restrict__ wq_out,
              const float4* __restrict__ wk_in,  float4* __restrict__ wk_out,
              const float4* __restrict__ wv_in,  float4* __restrict__ wv_out,
              const float4* __restrict__ wo_in,  float4* __restrict__ wo_out,
              const float* __restrict__ rel, float* __restrict__ slr)
{
    const int b = blockIdx.x;
    const float4* src;
    float4* dst;
    int base;
    if (b < NB_X)                    { src = xq_in;  dst = xq_out;  base = b * 1024; }
    else if (b < 2 * NB_X)           { src = xkv_in; dst = xkv_out; base = (b - NB_X) * 1024; }
    else if (b < 2 * NB_X + NB_W)    { src = wq_in;  dst = wq_out;  base = (b - 2 * NB_X) * 1024; }
    else if (b < 2 * NB_X + 2 * NB_W){ src = wk_in;  dst = wk_out;  base = (b - 2 * NB_X - NB_W) * 1024; }
    else if (b < 2 * NB_X + 3 * NB_W){ src = wv_in;  dst = wv_out;  base = (b - 2 * NB_X - 2 * NB_W) * 1024; }
    else                             { src = wo_in;  dst = wo_out;  base = (b - 2 * NB_X - 3 * NB_W) * 1024; }

    const int i0 = base + threadIdx.x;
    float4 v[4];
    #pragma unroll
    for (int j = 0; j < 4; j++) v[j] = src[i0 + j * 256];
    #pragma unroll
    for (int j = 0; j < 4; j++) {
        v[j].x = f2tf32(v[j].x); v[j].y = f2tf32(v[j].y);
        v[j].z = f2tf32(v[j].z); v[j].w = f2tf32(v[j].w);
        dst[i0 + j * 256] = v[j];
    }

    // slr: BATCH*NKVL = 4096 = 16 blocks x 256 threads
    if (b < 16) {
        const int i = b * 256 + threadIdx.x;
        slr[i] = logf(fmaxf(rel[i], 1e-6f));
    }
}

// ============================================================
// GEMM-NT (R9 proven):  C = (A W^T + bias) * gate?
// BM=BN=128, BK=32, 256 threads, 2-stage cp.async, 2 CTAs/SM.
// ============================================================
#define BM 128
#define BN 128
#define BK 32
#define SAo 36   // padded smem row stride (floats); frag LDS conflict-free

template<bool GATE, bool ROUND>
__global__ __launch_bounds__(256, 2)
void gemm_nt(const float* __restrict__ A, const float* __restrict__ W,
             const float* __restrict__ bias, const float* __restrict__ gate,
             float* __restrict__ C, int M, int N, int K)
{
    extern __shared__ float sm[];
    const uint32_t sbase = smem_u32(sm);

    const int tid  = threadIdx.x;
    const int wid  = tid >> 5;
    const int lane = tid & 31;
    const int g    = lane >> 2;
    const int t    = lane & 3;
    const int m0 = blockIdx.y * BM;
    const int n0 = blockIdx.x * BN;
    const int wm = (wid >> 2) * 64;
    const int wn = (wid & 3) * 32;

    const int lr = tid >> 3;              // 0..31
    const int lc = (tid & 7) * 4;         // 0..28

    float acc[4][4][4];
    #pragma unroll
    for (int i = 0; i < 4; i++)
        #pragma unroll
        for (int j = 0; j < 4; j++)
            #pragma unroll
            for (int c = 0; c < 4; c++) acc[i][j][c] = 0.f;

    const float* Ag = A + (size_t)(m0 + lr) * K + lc;
    const float* Bg = W + (size_t)(n0 + lr) * K + lc;

    auto issue_tile = [&](int kt, int s) {
        const int kc = kt * BK;
        #pragma unroll
        for (int i = 0; i < 4; i++) {
            const uint32_t da = sbase +
                (uint32_t)((s * BM * SAo + (lr + 32 * i) * SAo + lc) * 4);
            cp_a16(da, Ag + (size_t)(32 * i) * K + kc);
            const uint32_t db = sbase +
                (uint32_t)(((2 * BM * SAo) + s * BN * SAo + (lr + 32 * i) * SAo + lc) * 4);
            cp_a16(db, Bg + (size_t)(32 * i) * K + kc);
        }
        asm volatile("cp.async.commit_group;" ::: "memory");
    };

    issue_tile(0, 0);

    const int KT = K / BK;
    for (int kt = 0; kt < KT; kt++) {
        const int s = kt & 1;
        if (kt + 1 < KT) {
            issue_tile(kt + 1, s ^ 1);
            asm volatile("cp.async.wait_group 1;" ::: "memory");
        } else {
            asm volatile("cp.async.wait_group 0;" ::: "memory");
        }
        __syncthreads();

        const float* Ab = sm + s * BM * SAo + wm * SAo;
        const float* Bb = sm + 2 * BM * SAo + s * BN * SAo + wn * SAo;
        #pragma unroll
        for (int ks = 0; ks < 4; ks++) {
            const int kk = ks * 8;
            uint32_t af[4][4];
            #pragma unroll
            for (int mi = 0; mi < 4; mi++) {
                const float* p = Ab + (mi * 16 + g) * SAo + kk + t;
                af[mi][0] = __float_as_uint(p[0]);
                af[mi][1] = __float_as_uint(p[8 * SAo]);
                af[mi][2] = __float_as_uint(p[4]);
                af[mi][3] = __float_as_uint(p[8 * SAo + 4]);
            }
            uint32_t bf[4][2];
            #pragma unroll
            for (int ni = 0; ni < 4; ni++) {
                const float* p = Bb + (ni * 8 + g) * SAo + kk + t;
                bf[ni][0] = __float_as_uint(p[0]);
                bf[ni][1] = __float_as_uint(p[4]);
            }
            #pragma unroll
            for (int mi = 0; mi < 4; mi++)
                #pragma unroll
                for (int ni = 0; ni < 4; ni++)
                    mma_tf32(acc[mi][ni], af[mi], bf[ni]);
        }
        __syncthreads();
    }

    // epilogue
    #pragma unroll
    for (int ni = 0; ni < 4; ni++) {
        const int cc = n0 + wn + ni * 8 + 2 * t;
        const float b0 = bias[cc];
        const float b1 = bias[cc + 1];
        #pragma unroll
        for (int mi = 0; mi < 4; mi++) {
            const int rr = m0 + wm + mi * 16 + g;
            float v0 = acc[mi][ni][0] + b0;
            float v1 = acc[mi][ni][1] + b1;
            float v2 = acc[mi][ni][2] + b0;
            float v3 = acc[mi][ni][3] + b1;
            if (GATE) {
                const float g0 = gate[rr];
                const float g1 = gate[rr + 8];
                v0 *= g0; v1 *= g0; v2 *= g1; v3 *= g1;
            }
            if (ROUND) {
                v0 = f2tf32(v0); v1 = f2tf32(v1);
                v2 = f2tf32(v2); v3 = f2tf32(v3);
            }
            *(float2*)(C + (size_t)rr * N + cc)       = make_float2(v0, v1);
            *(float2*)(C + (size_t)(rr + 8) * N + cc) = make_float2(v2, v3);
        }
    }
}

// ============================================================
// Flash attention (R15 proven): 128 threads (4 warps), warp = 32 q-rows.
// K/V loaded via cp.async into row-major smem tiles (double-buffered):
//   Kt[kv][d]: stride 68  -> frag LDS bank = g*4+t  (conflict-free)
//   Vt[kv][d]: stride 72  -> frag LDS bank = t*8+g  (conflict-free)
// No scatter STS, no prefetch registers.  slr read via LDG (cached).
// Pf: per-warp P relayout buffer (C-frag -> A-frag).
// ============================================================
#define KS_STR  68
#define VS_STR  72
#define K0_OFF  0
#define K1_OFF  4352              // 64*68
#define V0_OFF  8704
#define V1_OFF  13312             // + 64*72
#define PF_OFF  17920
#define QS_OFF  0                 // alias over K/V buffers (dead after prologue)
#define QS_STR  68
#define FATT_FLOATS 26112         // 17920 + 8192
#define FATT_SMEM   (FATT_FLOATS * 4)   // 104448 B

__global__ __launch_bounds__(128, 2)
void flash_attn(const float* __restrict__ Q, const float* __restrict__ Kg,
                const float* __restrict__ V, const float* __restrict__ slrg,
                float* __restrict__ O)
{
    extern __shared__ float sm[];
    float* Pf = sm + PF_OFF;
    float* Qs = sm + QS_OFF;
    const uint32_t sbase = smem_u32(sm);

    const int tid  = threadIdx.x;
    const int wid  = tid >> 5;
    const int lane = tid & 31;
    const int g    = lane >> 2;
    const int t    = lane & 3;
    const int q0   = blockIdx.x * 128;
    const int h    = blockIdx.y;
    const int b    = blockIdx.z;
    const int col0 = h * HDIM;
    const int wq   = wid * 32;

    // ---- stage Q tile (coalesced), extract frags to registers ----
    #pragma unroll
    for (int i = 0; i < 16; i++) {
        const int chunk = tid + 128 * i;
        const int row = chunk >> 4;
        const int c4q = (chunk & 15) * 4;
        float4 v = *(const float4*)(Q + (size_t)(b * NQL + q0 + row) * DIMC + col0 + c4q);
        *(float4*)(Qs + row * QS_STR + c4q) = v;
    }
    __syncthreads();

    uint32_t qf[2][8][4];
    #pragma unroll
    for (int mi = 0; mi < 2; mi++)
        #pragma unroll
        for (int ks = 0; ks < 8; ks++) {
            const float* p = Qs + (wq + mi * 16 + g) * QS_STR + ks * 8 + t;
            qf[mi][ks][0] = __float_as_uint(p[0]);
            qf[mi][ks][1] = __float_as_uint(p[8 * QS_STR]);
            qf[mi][ks][2] = __float_as_uint(p[4]);
            qf[mi][ks][3] = __float_as_uint(p[8 * QS_STR + 4]);
        }
    __syncthreads();   // Qs dead; smem free for K/V buffers

    // ---- cp.async loader geometry: thread covers 8 rows x 16B ----
    const int r0 = tid >> 4;          // 0..7
    const int c4 = (tid & 15) * 4;    // 0..60
    const float* Kbase = Kg + (size_t)b * NKVL * DIMC + col0 + c4;
    const float* Vbase = V  + (size_t)b * NKVL * DIMC + col0 + c4;

    auto issue_kv = [&](int kt, int bu) {
        const uint32_t ko = sbase + (uint32_t)(((bu ? K1_OFF : K0_OFF)) * 4);
        const uint32_t vo = sbase + (uint32_t)(((bu ? V1_OFF : V0_OFF)) * 4);
        #pragma unroll
        for (int i = 0; i < 8; i++) {
            const int row = r0 + 8 * i;
            const size_t go = (size_t)(kt * 64 + row) * DIMC;
            cp_a16(ko + (uint32_t)((row * KS_STR + c4) * 4), Kbase + go);
            cp_a16(vo + (uint32_t)((row * VS_STR + c4) * 4), Vbase + go);
        }
        asm volatile("cp.async.commit_group;" ::: "memory");
    };

    issue_kv(0, 0);

    float mrow[2][2], lrow[2][2];
    #pragma unroll
    for (int mi = 0; mi < 2; mi++) { mrow[mi][0] = mrow[mi][1] = -1e30f; lrow[mi][0] = lrow[mi][1] = 0.f; }
    float oacc[2][8][4];
    #pragma unroll
    for (int mi = 0; mi < 2; mi++)
        #pragma unroll
        for (int nb = 0; nb < 8; nb++)
            #pragma unroll
            for (int c = 0; c < 4; c++) oacc[mi][nb][c] = 0.f;

    const float* slr_b = slrg + b * NKVL;

    int buf = 0;
    const int KT = NKVL / 64;
    for (int kt = 0; kt < KT; kt++) {
        asm volatile("cp.async.wait_group 0;" ::: "memory");
        __syncthreads();                       // tile kt visible; prev buffers free
        if (kt + 1 < KT) issue_kv(kt + 1, buf ^ 1);

        const float* Kt = sm + (buf ? K1_OFF : K0_OFF);
        const float* Vt = sm + (buf ? V1_OFF : V0_OFF);

        // ---- S = Q K^T  (K-frags loaded once, shared by both halves) ----
        float sacc[2][8][4];
        #pragma unroll
        for (int mi = 0; mi < 2; mi++)
            #pragma unroll
            for (int nb = 0; nb < 8; nb++)
                #pragma unroll
                for (int c = 0; c < 4; c++) sacc[mi][nb][c] = 0.f;
        #pragma unroll
        for (int ks = 0; ks < 8; ks++) {
            uint32_t bf[8][2];
            #pragma unroll
            for (int nb = 0; nb < 8; nb++) {
                const float* p = Kt + (nb * 8 + g) * KS_STR + ks * 8 + t;
                bf[nb][0] = __float_as_uint(p[0]);
                bf[nb][1] = __float_as_uint(p[4]);
            }
            #pragma unroll
            for (int nb = 0; nb < 8; nb++) {
                mma_tf32(sacc[0][nb], qf[0][ks], bf[nb]);
                mma_tf32(sacc[1][nb], qf[1][ks], bf[nb]);
            }
        }

        // ---- softmax per 16-row half; write P in PV A-frag layout ----
        const int slr0 = kt * 64 + 2 * t;
        #pragma unroll
        for (int mi = 0; mi < 2; mi++) {
            float mt0 = -1e30f, mt1 = -1e30f;
            #pragma unroll
            for (int nb = 0; nb < 8; nb++) {
                const float2 l2 = *(const float2*)(slr_b + slr0 + nb * 8);
                sacc[mi][nb][0] = sacc[mi][nb][0] * 0.125f + l2.x;
                sacc[mi][nb][1] = sacc[mi][nb][1] * 0.125f + l2.y;
                sacc[mi][nb][2] = sacc[mi][nb][2] * 0.125f + l2.x;
                sacc[mi][nb][3] = sacc[mi][nb][3] * 0.125f + l2.y;
                mt0 = fmaxf(mt0, fmaxf(sacc[mi][nb][0], sacc[mi][nb][1]));
                mt1 = fmaxf(mt1, fmaxf(sacc[mi][nb][2], sacc[mi][nb][3]));
            }
            mt0 = fmaxf(mt0, __shfl_xor_sync(0xffffffffu, mt0, 1));
            mt0 = fmaxf(mt0, __shfl_xor_sync(0xffffffffu, mt0, 2));
            mt1 = fmaxf(mt1, __shfl_xor_sync(0xffffffffu, mt1, 1));
            mt1 = fmaxf(mt1, __shfl_xor_sync(0xffffffffu, mt1, 2));
            const float mn0 = fmaxf(mrow[mi][0], mt0);
            const float mn1 = fmaxf(mrow[mi][1], mt1);

            const int t2 = (2 * t) & 3;
            const int hk = t >> 1;
            const int sg = (g >> 1) & 3;
            float* pw = Pf + ((wid * 2 + mi) * 8) * 128;
            float rs0 = 0.f, rs1 = 0.f;
            #pragma unroll
            for (int nb = 0; nb < 8; nb++) {
                const float p0 = __expf(sacc[mi][nb][0] - mn0);
                const float p1 = __expf(sacc[mi][nb][1] - mn0);
                const float p2 = __expf(sacc[mi][nb][2] - mn1);
                const float p3 = __expf(sacc[mi][nb][3] - mn1);
                rs0 += p0 + p1;
                rs1 += p2 + p3;
                float* base = pw + nb * 128;
                const int l0s = g * 4 + (t2 ^ sg);
                const int l1s = g * 4 + ((t2 + 1) ^ sg);
                *(float2*)(base + l0s * 4 + 2 * hk) = make_float2(f2tf32(p0), f2tf32(p2));
                *(float2*)(base + l1s * 4 + 2 * hk) = make_float2(f2tf32(p1), f2tf32(p3));
            }
            rs0 += __shfl_xor_sync(0xffffffffu, rs0, 1);
            rs0 += __shfl_xor_sync(0xffffffffu, rs0, 2);
            rs1 += __shfl_xor_sync(0xffffffffu, rs1, 1);
            rs1 += __shfl_xor_sync(0xffffffffu, rs1, 2);

            const float al0 = __expf(mrow[mi][0] - mn0);
            const float al1 = __expf(mrow[mi][1] - mn1);
            lrow[mi][0] = lrow[mi][0] * al0 + rs0;
            lrow[mi][1] = lrow[mi][1] * al1 + rs1;
            mrow[mi][0] = mn0; mrow[mi][1] = mn1;
            #pragma unroll
            for (int nb = 0; nb < 8; nb++) {
                oacc[mi][nb][0] *= al0; oacc[mi][nb][1] *= al0;
                oacc[mi][nb][2] *= al1; oacc[mi][nb][3] *= al1;
            }
        }
        __syncwarp();   // Pf is per-warp private

        // ---- O += P V  (V-frags from row-major Vt, loaded once per ks) ----
        #pragma unroll
        for (int ks = 0; ks < 8; ks++) {
            uint32_t vf[8][2];
            #pragma unroll
            for (int nb = 0; nb < 8; nb++) {
                const float* p = Vt + (ks * 8 + t) * VS_STR + nb * 8 + g;
                vf[nb][0] = __float_as_uint(p[0]);
                vf[nb][1] = __float_as_uint(p[4 * VS_STR]);
            }
            const int pslot = g * 4 + (t ^ ((g >> 1) & 3));
            float4 a0 = *(const float4*)(Pf + ((wid * 2 + 0) * 8 + ks) * 128 + pslot * 4);
            float4 a1 = *(const float4*)(Pf + ((wid * 2 + 1) * 8 + ks) * 128 + pslot * 4);
            #pragma unroll
            for (int nb = 0; nb < 8; nb++) {
                mma_tf32(oacc[0][nb], (const uint32_t*)&a0, vf[nb]);
                mma_tf32(oacc[1][nb], (const uint32_t*)&a1, vf[nb]);
            }
        }
        buf ^= 1;
    }

    // ---- epilogue (round output: feeds final GEMM) ----
    #pragma unroll
    for (int mi = 0; mi < 2; mi++) {
        const float il0 = 1.f / lrow[mi][0];
        const float il1 = 1.f / lrow[mi][1];
        const size_t orow = (size_t)(b * NQL + q0 + wq + mi * 16 + g);
        #pragma unroll
        for (int nb = 0; nb < 8; nb++) {
            const int c = col0 + nb * 8 + 2 * t;
            *(float2*)(O + orow * DIMC + c) =
                make_float2(f2tf32(oacc[mi][nb][0] * il0), f2tf32(oacc[mi][nb][1] * il0));
            *(float2*)(O + (orow + 8) * DIMC + c) =
                make_float2(f2tf32(oacc[mi][nb][2] * il1), f2tf32(oacc[mi][nb][3] * il1));
        }
    }
}

// ============================================================
// Launch
// ============================================================
extern "C" void kernel_launch(void* const* d_in, const int* in_sizes, int n_in,
                              void* d_out, int out_size)
{
    (void)in_sizes; (void)n_in; (void)out_size;
    const float* qf  = (const float*)d_in[0];
    const float* kvf = (const float*)d_in[1];
    const float* rel = (const float*)d_in[2];
    const float* Wq  = (const float*)d_in[3];
    const float* bq  = (const float*)d_in[4];
    const float* Wk  = (const float*)d_in[5];
    const float* bk  = (const float*)d_in[6];
    const float* Wv  = (const float*)d_in[7];
    const float* bv  = (const float*)d_in[8];
    const float* Wo  = (const float*)d_in[9];
    const float* bo  = (const float*)d_in[10];
    float* out = (float*)d_out;

    float *pq, *pk, *pv, *pao, *pxq, *pxkv, *pwq, *pwk, *pwv, *pwo, *pslr;
    cudaGetSymbolAddress((void**)&pq,   g_q);
    cudaGetSymbolAddress((void**)&pk,   g_k);
    cudaGetSymbolAddress((void**)&pv,   g_v);
    cudaGetSymbolAddress((void**)&pao,  g_ao);
    cudaGetSymbolAddress((void**)&pxq,  g_xq);
    cudaGetSymbolAddress((void**)&pxkv, g_xkv);
    cudaGetSymbolAddress((void**)&pwq,  g_wq);
    cudaGetSymbolAddress((void**)&pwk,  g_wk);
    cudaGetSymbolAddress((void**)&pwv,  g_wv);
    cudaGetSymbolAddress((void**)&pwo,  g_wo);
    cudaGetSymbolAddress((void**)&pslr, g_slr);

    const int gemm_smem = (int)(2 * BM * SAo + 2 * BN * SAo) * 4;   // 73728 B

    cudaFuncSetAttribute(gemm_nt<false, true>,
                         cudaFuncAttributeMaxDynamicSharedMemorySize, gemm_smem);
    cudaFuncSetAttribute(gemm_nt<true, true>,
                         cudaFuncAttributeMaxDynamicSharedMemorySize, gemm_smem);
    cudaFuncSetAttribute(gemm_nt<false, false>,
                         cudaFuncAttributeMaxDynamicSharedMemorySize, gemm_smem);
    cudaFuncSetAttribute(flash_attn,
                         cudaFuncAttributeMaxDynamicSharedMemorySize, FATT_SMEM);

    // ---- fused prep: ONE launch for all tf32 rounding + log-reliability ----
    prep_all<<<PREP_BLOCKS, 256>>>(
        (const float4*)qf,  (float4*)pxq,
        (const float4*)kvf, (float4*)pxkv,
        (const float4*)Wq,  (float4*)pwq,
        (const float4*)Wk,  (float4*)pwk,
        (const float4*)Wv,  (float4*)pwv,
        (const float4*)Wo,  (float4*)pwo,
        rel, pslr);

    dim3 gg(DIMC / BN, MROWS / BM);   // (8, 32)
    gemm_nt<false, true><<<gg, 256, gemm_smem>>>(pxq,  pwq, bq, nullptr, pq, MROWS, DIMC, DIMC);
    gemm_nt<true,  true><<<gg, 256, gemm_smem>>>(pxkv, pwk, bk, rel,     pk, MROWS, DIMC, DIMC);
    gemm_nt<true,  true><<<gg, 256, gemm_smem>>>(pxkv, pwv, bv, rel,     pv, MROWS, DIMC, DIMC);

    flash_attn<<<dim3(NQL / 128, HEADS, BATCH), 128, FATT_SMEM>>>(pq, pk, pv, pslr, pao);

    gemm_nt<false, false><<<gg, 256, gemm_smem>>>(pao, pwo, bo, nullptr, out, MROWS, DIMC, DIMC);
}